// round 6
// baseline (speedup 1.0000x reference)
#include <cuda_runtime.h>
#include <cuda_bf16.h>
#include <cstdint>

// SSIM loss map: out = clip((1 - SSIM_3x3(x,y)) * 0.5, 0, 1)
// NCHW fp32, 16x3x512x512 = 48 planes of 512x512.
// Register-sliding, no shared memory, packed f32x2 math, one-iteration
// software pipeline. Interior y-blocks (30/32) take a branchless path with
// no row-bounds checks and the normalization constant hoisted.

#define IMG   512
#define ROWS  16          // output rows per thread
#define TPX   128         // threads per block; block covers TPX*2 = 256 cols

typedef unsigned long long u64;

// ---- packed f32x2 helpers (sm_100+) ----
__device__ __forceinline__ u64 pk(float x, float y) {
    u64 r; asm("mov.b64 %0, {%1, %2};" : "=l"(r) : "f"(x), "f"(y)); return r;
}
__device__ __forceinline__ float2 unpk(u64 v) {
    float2 r; asm("mov.b64 {%0, %1}, %2;" : "=f"(r.x), "=f"(r.y) : "l"(v)); return r;
}
__device__ __forceinline__ u64 add2(u64 a, u64 b) {
    u64 r; asm("add.rn.f32x2 %0, %1, %2;" : "=l"(r) : "l"(a), "l"(b)); return r;
}
__device__ __forceinline__ u64 sub2(u64 a, u64 b) {
    u64 r; asm("sub.rn.f32x2 %0, %1, %2;" : "=l"(r) : "l"(a), "l"(b)); return r;
}
__device__ __forceinline__ u64 mul2(u64 a, u64 b) {
    u64 r; asm("mul.rn.f32x2 %0, %1, %2;" : "=l"(r) : "l"(a), "l"(b)); return r;
}
__device__ __forceinline__ u64 fma2(u64 a, u64 b, u64 c) {
    u64 r; asm("fma.rn.f32x2 %0, %1, %2, %3;" : "=l"(r) : "l"(a), "l"(b), "l"(c)); return r;
}

struct Raw  { float2 a, b; };                   // this thread's float2 of x and y
struct Stat { u64 x, y, xx, yy, xy; };          // packed horizontal 3-tap sums

// Prefetch: LDGs only (no dependent consumption this iteration).
template<bool EDGE>
__device__ __forceinline__ Raw load_raw(const float* __restrict__ gxp,
                                        const float* __restrict__ gyp,
                                        int row, int c2)
{
    Raw r;
    if (EDGE && (unsigned)row >= (unsigned)IMG) {
        r.a = make_float2(0.f, 0.f);
        r.b = make_float2(0.f, 0.f);
        return r;
    }
    const size_t ro = (size_t)row * IMG;
    r.a = *((const float2*)(gxp + ro) + c2);
    r.b = *((const float2*)(gyp + ro) + c2);
    return r;
}

// Consume: shuffles on registers loaded >=1 iteration ago; edge lanes pull
// their neighbor scalar from L1 (loaded by the adjacent warp last iteration).
template<bool EDGE>
__device__ __forceinline__ Stat make_stats(const Raw& w,
                                           const float* __restrict__ gxp,
                                           const float* __restrict__ gyp,
                                           int row, int c2,
                                           bool pl, bool pr, bool okL, bool okR)
{
    float aL = __shfl_up_sync(0xffffffffu, w.a.y, 1);
    float bL = __shfl_up_sync(0xffffffffu, w.b.y, 1);
    float aR = __shfl_down_sync(0xffffffffu, w.a.x, 1);
    float bR = __shfl_down_sync(0xffffffffu, w.b.x, 1);

    const bool rok = !EDGE || ((unsigned)row < (unsigned)IMG);
    const size_t ro = (size_t)row * IMG;
    if (pl) {
        bool v = okL && rok;
        aL = v ? gxp[ro + (c2 * 2 - 1)] : 0.f;
        bL = v ? gyp[ro + (c2 * 2 - 1)] : 0.f;
    }
    if (pr) {
        bool v = okR && rok;
        aR = v ? gxp[ro + (c2 * 2 + 2)] : 0.f;
        bR = v ? gyp[ro + (c2 * 2 + 2)] : 0.f;
    }

    Stat s;
    float sa = w.a.x + w.a.y;
    s.x = pk(aL + sa, sa + aR);
    float sb = w.b.x + w.b.y;
    s.y = pk(bL + sb, sb + bR);
    float pa = fmaf(w.a.x, w.a.x, w.a.y * w.a.y);
    s.xx = pk(fmaf(aL, aL, pa), fmaf(aR, aR, pa));
    float pb = fmaf(w.b.x, w.b.x, w.b.y * w.b.y);
    s.yy = pk(fmaf(bL, bL, pb), fmaf(bR, bR, pb));
    float pm = fmaf(w.a.x, w.b.x, w.a.y * w.b.y);
    s.xy = pk(fmaf(aL, bL, pm), fmaf(aR, bR, pm));
    return s;
}

template<bool EDGE>
__device__ __forceinline__ void run_tile(const float* __restrict__ gxp,
                                         const float* __restrict__ gyp,
                                         float2* __restrict__ out2,
                                         int h0, int c2,
                                         bool pl, bool pr, bool okL, bool okR,
                                         float2 rcx)
{
    const float THIRD = 1.f / 3.f;
    const u64 TWO2 = pk(2.f, 2.f);
    const u64 C12  = pk(1e-4f, 1e-4f);
    const u64 C22  = pk(9e-4f, 9e-4f);
    const u64 EPS2 = pk(1e-12f, 1e-12f);

    // interior: cy == 3 for every row -> hoist the normalization constant
    const u64 inv_i = pk(rcx.x * THIRD, rcx.y * THIRD);

    Stat p = make_stats<EDGE>(load_raw<EDGE>(gxp, gyp, h0 - 1, c2),
                              gxp, gyp, h0 - 1, c2, pl, pr, okL, okR);
    Stat c = make_stats<EDGE>(load_raw<EDGE>(gxp, gyp, h0, c2),
                              gxp, gyp, h0, c2, pl, pr, okL, okR);
    Raw rn = load_raw<EDGE>(gxp, gyp, h0 + 1, c2);

    #pragma unroll
    for (int r = 0; r < ROWS; r++) {
        const int h = h0 + r;

        // prefetch row h+2 (consumed next iteration)
        Raw rf = load_raw<EDGE>(gxp, gyp, h + 2, c2);

        // consume row h+1
        Stat n = make_stats<EDGE>(rn, gxp, gyp, h + 1, c2, pl, pr, okL, okR);

        u64 inv;
        if (EDGE) {
            const float rcy = (h == 0 || h == IMG - 1) ? 0.5f : THIRD;
            inv = pk(rcx.x * rcy, rcx.y * rcy);
        } else {
            inv = inv_i;
        }

        // vertical 3-tap sums (packed)
        u64 Sx  = add2(add2(p.x,  c.x),  n.x);
        u64 Sy  = add2(add2(p.y,  c.y),  n.y);
        u64 Sxx = add2(add2(p.xx, c.xx), n.xx);
        u64 Syy = add2(add2(p.yy, c.yy), n.yy);
        u64 Sxy = add2(add2(p.xy, c.xy), n.xy);

        // packed SSIM epilogue
        u64 mux = mul2(Sx, inv);
        u64 muy = mul2(Sy, inv);
        u64 mmx  = mul2(mux, mux);
        u64 mmy  = mul2(muy, muy);
        u64 mmxy = mul2(mux, muy);
        u64 sigx  = sub2(mul2(Sxx, inv), mmx);
        u64 sigy  = sub2(mul2(Syy, inv), mmy);
        u64 sigxy = sub2(mul2(Sxy, inv), mmxy);

        u64 t1  = fma2(mmxy, TWO2, C12);
        u64 t2  = fma2(sigxy, TWO2, C22);
        u64 num = mul2(t1, t2);
        u64 d1  = add2(add2(mmx, mmy), C12);
        u64 d2  = add2(add2(sigx, sigy), C22);
        u64 den = fma2(d1, d2, EPS2);

        float2 fn = unpk(num);
        float2 fd = unpk(den);
        // one reciprocal for both columns: s_i = n_i * d_other * (1/(d0*d1))
        float rp = __fdividef(1.f, fd.x * fd.y);
        float s0 = fn.x * fd.y * rp;
        float s1 = fn.y * fd.x * rp;
        float2 o;
        o.x = fminf(fmaxf(fmaf(s0, -0.5f, 0.5f), 0.f), 1.f);
        o.y = fminf(fmaxf(fmaf(s1, -0.5f, 0.5f), 0.f), 1.f);

        out2[(size_t)h * (IMG / 2) + c2] = o;

        p = c;
        c = n;
        rn = rf;
    }
}

__global__ __launch_bounds__(TPX, 8)
void ssim_kernel(const float* __restrict__ gx,
                 const float* __restrict__ gy,
                 float* __restrict__ gout)
{
    const int tx   = threadIdx.x;
    const int lane = tx & 31;
    const bool pl = (lane == 0);
    const bool pr = (lane == 31);
    const int c2 = blockIdx.x * TPX + tx;          // float2 column index, 0..255
    const bool okL = (c2 > 0);
    const bool okR = (c2 < IMG / 2 - 1);
    const size_t base = (size_t)blockIdx.z * (IMG * IMG);
    const float* gxp = gx + base;
    const float* gyp = gy + base;
    float2* out2 = (float2*)(gout + base);
    const int h0 = blockIdx.y * ROWS;

    const float THIRD = 1.f / 3.f;
    float2 rcx = make_float2(okL ? THIRD : 0.5f,
                             okR ? THIRD : 0.5f);

    // interior y-blocks: all loaded rows in-bounds, all cy == 3
    if (h0 >= 1 && h0 + ROWS + 1 <= IMG - 1)
        run_tile<false>(gxp, gyp, out2, h0, c2, pl, pr, okL, okR, rcx);
    else
        run_tile<true >(gxp, gyp, out2, h0, c2, pl, pr, okL, okR, rcx);
}

extern "C" void kernel_launch(void* const* d_in, const int* in_sizes, int n_in,
                              void* d_out, int out_size)
{
    const float* x = (const float*)d_in[0];
    const float* y = (const float*)d_in[1];
    float* out = (float*)d_out;

    dim3 block(TPX, 1, 1);                            // 128 threads
    dim3 grid(IMG / (2 * TPX), IMG / ROWS, 16 * 3);   // 2 x 32 x 48 = 3072
    ssim_kernel<<<grid, block>>>(x, y, out);
}